// round 6
// baseline (speedup 1.0000x reference)
#include <cuda_runtime.h>
#include <cuda_fp16.h>
#include <mma.h>
#include <cstdint>
using namespace nvcuda;

#define BB 8
#define NN 3136
#define CC 512
#define C4 128
#define NHEADS 8
#define P2 784
#define MKV 196
#define MTOK (BB*NN)

// ---------------- scratch ----------------
__device__ __half g_xh  [MTOK*CC];
__device__ __half g_qh  [MTOK*CC];
__device__ float  g_rtmp[MTOK*C4];
__device__ __half g_dwt [BB*P2*CC];       // NHWC
__device__ __half g_c3  [BB*P2*CC];       // NHWC
__device__ float  g_kvin[BB*MKV*CC];
__device__ __half g_kvinh[BB*MKV*CC];
__device__ __half g_kvh [BB*MKV*2*CC];
__device__ __half g_cath[MTOK*(CC+C4)];
__device__ __half g_qwh  [CC*CC];
__device__ __half g_rwh  [C4*CC];
__device__ __half g_fwh  [CC*CC*9];       // [oc][kyx][ic]
__device__ __half g_kvewh[CC*CC*4];       // [oc][kyx][ic]
__device__ __half g_kvwh [2*CC*CC];
__device__ __half g_pwh  [CC*(CC+C4)];

// ---------------- cp.async helpers ----------------
__device__ __forceinline__ unsigned int s2u(const void* p) {
    return (unsigned int)__cvta_generic_to_shared(p);
}
__device__ __forceinline__ void cp16(unsigned int d, const void* s) {
    asm volatile("cp.async.cg.shared.global [%0], [%1], 16;" :: "r"(d), "l"(s) : "memory");
}
__device__ __forceinline__ void cp16p(unsigned int d, const void* s, bool pred) {
    int sz = pred ? 16 : 0;
    asm volatile("cp.async.cg.shared.global [%0], [%1], 16, %2;" :: "r"(d), "l"(s), "r"(sz) : "memory");
}
__device__ __forceinline__ void cpcommit() { asm volatile("cp.async.commit_group;" ::: "memory"); }
__device__ __forceinline__ void cpwait0() { asm volatile("cp.async.wait_group 0;" ::: "memory"); }
__device__ __forceinline__ void cpwait1() { asm volatile("cp.async.wait_group 1;" ::: "memory"); }

// ---------------- conversion kernels ----------------
__global__ void f2h(const float* __restrict__ s, __half* __restrict__ d, int n) {
    int i = blockIdx.x * blockDim.x + threadIdx.x;
    if (i < n) d[i] = __float2half(s[i]);
}
__global__ void reorder_w3(const float* __restrict__ w, __half* __restrict__ o) {
    int idx = blockIdx.x * 256 + threadIdx.x;
    if (idx >= 512 * 4608) return;
    int oc = idx / 4608;
    int r = idx - oc * 4608;
    int kyx = r >> 9;
    int ic = r & 511;
    o[idx] = __float2half(w[((long)(oc * 512 + ic)) * 9 + kyx]);
}
__global__ void reorder_w2(const float* __restrict__ w, __half* __restrict__ o) {
    int idx = blockIdx.x * 256 + threadIdx.x;
    if (idx >= 512 * 2048) return;
    int oc = idx >> 11;
    int r = idx & 2047;
    int kyx = r >> 9;
    int ic = r & 511;
    o[idx] = __float2half(w[((long)(oc * 512 + ic)) * 4 + kyx]);
}

__device__ __forceinline__ void st_out(float* p, float v) { *p = v; }
__device__ __forceinline__ void st_out(__half* p, float v) { *p = __float2half(v); }

// =====================================================================
// gemm core: 256x128 block tile, BK=32, 3-stage cp.async, 8 warps 64x64
// loadTile(kt, buf) fills As[buf] (256x32) and Bs[buf] (128x32)
// =====================================================================
#define GEMM_SMEM (3*256*48*2 + 3*128*48*2)
typedef wmma::fragment<wmma::accumulator, 16, 16, 16, float> AccFrag;

template<typename LT>
__device__ __forceinline__ void gemm_core(char* smem, int KT, LT loadTile,
                                          AccFrag (&acc)[4][4], int wm, int wn) {
    __half* As = (__half*)smem;
    __half* Bs = (__half*)(smem + 73728);
    #pragma unroll
    for (int i = 0; i < 4; i++)
        #pragma unroll
        for (int j = 0; j < 4; j++) wmma::fill_fragment(acc[i][j], 0.f);
    loadTile(0, 0); cpcommit();
    if (KT > 1) { loadTile(1, 1); cpcommit(); }
    for (int kt = 0; kt < KT; kt++) {
        if (kt < KT - 1) cpwait1(); else cpwait0();
        __syncthreads();
        if (kt + 2 < KT) { loadTile(kt + 2, (kt + 2) % 3); cpcommit(); }
        int cur = kt % 3;
        #pragma unroll
        for (int kk = 0; kk < 32; kk += 16) {
            wmma::fragment<wmma::matrix_a, 16, 16, 16, __half, wmma::row_major> af[4];
            wmma::fragment<wmma::matrix_b, 16, 16, 16, __half, wmma::col_major> bf[4];
            #pragma unroll
            for (int i = 0; i < 4; i++)
                wmma::load_matrix_sync(af[i], &As[(cur * 256 + wm * 64 + i * 16) * 48 + kk], 48);
            #pragma unroll
            for (int j = 0; j < 4; j++)
                wmma::load_matrix_sync(bf[j], &Bs[(cur * 128 + wn * 64 + j * 16) * 48 + kk], 48);
            #pragma unroll
            for (int i = 0; i < 4; i++)
                #pragma unroll
                for (int j = 0; j < 4; j++)
                    wmma::mma_sync(acc[i][j], af[i], bf[j], acc[i][j]);
        }
        __syncthreads();
    }
}

// =====================================================================
// gemm16: C[m,n] = sum_k A[m,k] B[n,k] + bias[n]
// =====================================================================
template<typename OT>
__global__ __launch_bounds__(256)
void gemm16(const __half* __restrict__ A, const __half* __restrict__ B,
            const float* __restrict__ bias, OT* __restrict__ C,
            int M, int N, int K, int ldc) {
    extern __shared__ char smem[];
    __half* As = (__half*)smem;
    __half* Bs = (__half*)(smem + 73728);
    float*  Es = (float*)smem;
    int tid = threadIdx.x;
    int warp = tid >> 5;
    int lane = tid & 31;
    int wm = warp >> 1;
    int wn = warp & 1;
    int m0 = blockIdx.y * 256;
    int n0 = blockIdx.x * 128;
    AccFrag acc[4][4];
    auto loadTile = [&](int kt, int buf) {
        int k0 = kt << 5;
        #pragma unroll
        for (int i = 0; i < 4; i++) {
            int c = tid + i * 256;
            int row = c >> 2;
            int off = (c & 3) * 8;
            int m = m0 + row;
            bool ok = (m < M);
            cp16p(s2u(&As[(buf * 256 + row) * 48 + off]), &A[(long)(ok ? m : 0) * K + k0 + off], ok);
        }
        #pragma unroll
        for (int i = 0; i < 2; i++) {
            int c = tid + i * 256;
            int row = c >> 2;
            int off = (c & 3) * 8;
            cp16(s2u(&Bs[(buf * 128 + row) * 48 + off]), &B[(long)(n0 + row) * K + k0 + off]);
        }
    };
    gemm_core(smem, K >> 5, loadTile, acc, wm, wn);
    #pragma unroll
    for (int i = 0; i < 4; i++)
        #pragma unroll
        for (int j = 0; j < 4; j++) {
            wmma::store_matrix_sync(&Es[warp * 384], acc[i][j], 24, wmma::mem_row_major);
            __syncwarp();
            #pragma unroll
            for (int e = 0; e < 8; e++) {
                int idx = lane + e * 32;
                int r = idx >> 4;
                int c = idx & 15;
                int m = m0 + wm * 64 + i * 16 + r;
                int n = n0 + wn * 64 + j * 16 + c;
                if (m < M) st_out(&C[(long)m * ldc + n], Es[warp * 384 + r * 24 + c] + bias[n]);
            }
            __syncwarp();
        }
}

// =====================================================================
// conv3x3 implicit GEMM (NHWC) + BN + ReLU -> fp16; M=6272,N=512,K=4608
// =====================================================================
__global__ __launch_bounds__(256)
void conv3_g(const __half* __restrict__ dwt, const __half* __restrict__ w,
             const float* __restrict__ cb, const float* __restrict__ cg,
             const float* __restrict__ cbeta, __half* __restrict__ out) {
    extern __shared__ char smem[];
    __half* As = (__half*)smem;
    __half* Bs = (__half*)(smem + 73728);
    float*  Es = (float*)smem;
    int tid = threadIdx.x;
    int warp = tid >> 5;
    int lane = tid & 31;
    int wm = warp >> 1;
    int wn = warp & 1;
    int m0 = blockIdx.y * 256;
    int n0 = blockIdx.x * 128;
    int pre_b[4], pre_y[4], pre_x[4];
    bool pre_v[4];
    #pragma unroll
    for (int i = 0; i < 4; i++) {
        int c = tid + i * 256;
        int row = c >> 2;
        int m = m0 + row;
        pre_v[i] = (m < BB * P2);
        int mm = pre_v[i] ? m : 0;
        int b = mm / P2;
        int p = mm - b * P2;
        pre_b[i] = b;
        pre_y[i] = p / 28;
        pre_x[i] = p - (p / 28) * 28;
    }
    AccFrag acc[4][4];
    auto loadTile = [&](int kt, int buf) {
        int k0 = kt << 5;
        #pragma unroll
        for (int i = 0; i < 4; i++) {
            int c = tid + i * 256;
            int row = c >> 2;
            int off = (c & 3) * 8;
            int k = k0 + off;
            int kyx = k >> 9;
            int ic = k & 511;
            int ky = kyx / 3;
            int kx = kyx - ky * 3;
            int iy = pre_y[i] + ky - 1;
            int ix = pre_x[i] + kx - 1;
            bool ok = pre_v[i] && iy >= 0 && iy < 28 && ix >= 0 && ix < 28;
            int iyc = ok ? iy : 0;
            int ixc = ok ? ix : 0;
            cp16p(s2u(&As[(buf * 256 + row) * 48 + off]),
                  &dwt[((long)(pre_b[i] * P2 + iyc * 28 + ixc) << 9) + ic], ok);
        }
        #pragma unroll
        for (int i = 0; i < 2; i++) {
            int c = tid + i * 256;
            int row = c >> 2;
            int off = (c & 3) * 8;
            cp16(s2u(&Bs[(buf * 128 + row) * 48 + off]), &w[(long)(n0 + row) * 4608 + k0 + off]);
        }
    };
    gemm_core(smem, 144, loadTile, acc, wm, wn);
    const float invs = rsqrtf(1.f + 1e-5f);
    #pragma unroll
    for (int i = 0; i < 4; i++)
        #pragma unroll
        for (int j = 0; j < 4; j++) {
            wmma::store_matrix_sync(&Es[warp * 384], acc[i][j], 24, wmma::mem_row_major);
            __syncwarp();
            #pragma unroll
            for (int e = 0; e < 8; e++) {
                int idx = lane + e * 32;
                int r = idx >> 4;
                int c = idx & 15;
                int m = m0 + wm * 64 + i * 16 + r;
                int n = n0 + wn * 64 + j * 16 + c;
                if (m < BB * P2) {
                    float v = Es[warp * 384 + r * 24 + c] + cb[n];
                    v = v * (cg[n] * invs) + cbeta[n];
                    out[((long)m << 9) + n] = __float2half(fmaxf(v, 0.f));
                }
            }
            __syncwarp();
        }
}

// =====================================================================
// kve 2x2 s2 conv implicit GEMM; M=1568,N=512,K=2048 -> fp32 + bias
// =====================================================================
__global__ __launch_bounds__(256)
void kve_g(const __half* __restrict__ c3, const __half* __restrict__ w,
           const float* __restrict__ bias, float* __restrict__ out) {
    extern __shared__ char smem[];
    __half* As = (__half*)smem;
    __half* Bs = (__half*)(smem + 73728);
    float*  Es = (float*)smem;
    int tid = threadIdx.x;
    int warp = tid >> 5;
    int lane = tid & 31;
    int wm = warp >> 1;
    int wn = warp & 1;
    int m0 = blockIdx.y * 256;
    int n0 = blockIdx.x * 128;
    int pre_s[4];
    bool pre_v[4];
    #pragma unroll
    for (int i = 0; i < 4; i++) {
        int c = tid + i * 256;
        int row = c >> 2;
        int m = m0 + row;
        pre_v[i] = (m < BB * MKV);
        int mm = pre_v[i] ? m : 0;
        int b = mm / MKV;
        int p = mm - b * MKV;
        int oy = p / 14;
        int ox = p - (p / 14) * 14;
        pre_s[i] = b * P2 + 2 * oy * 28 + 2 * ox;
    }
    AccFrag acc[4][4];
    auto loadTile = [&](int kt, int buf) {
        int k0 = kt << 5;
        #pragma unroll
        for (int i = 0; i < 4; i++) {
            int c = tid + i * 256;
            int row = c >> 2;
            int off = (c & 3) * 8;
            int k = k0 + off;
            int kyx = k >> 9;
            int ic = k & 511;
            int ky = kyx >> 1;
            int kx = kyx & 1;
            cp16p(s2u(&As[(buf * 256 + row) * 48 + off]),
                  &c3[((long)(pre_s[i] + ky * 28 + kx) << 9) + ic], pre_v[i]);
        }
        #pragma unroll
        for (int i = 0; i < 2; i++) {
            int c = tid + i * 256;
            int row = c >> 2;
            int off = (c & 3) * 8;
            cp16(s2u(&Bs[(buf * 128 + row) * 48 + off]), &w[(long)(n0 + row) * 2048 + k0 + off]);
        }
    };
    gemm_core(smem, 64, loadTile, acc, wm, wn);
    #pragma unroll
    for (int i = 0; i < 4; i++)
        #pragma unroll
        for (int j = 0; j < 4; j++) {
            wmma::store_matrix_sync(&Es[warp * 384], acc[i][j], 24, wmma::mem_row_major);
            __syncwarp();
            #pragma unroll
            for (int e = 0; e < 8; e++) {
                int idx = lane + e * 32;
                int r = idx >> 4;
                int c = idx & 15;
                int m = m0 + wm * 64 + i * 16 + r;
                int n = n0 + wn * 64 + j * 16 + c;
                if (m < BB * MKV) out[(long)m * CC + n] = Es[warp * 384 + r * 24 + c] + bias[n];
            }
            __syncwarp();
        }
}

// ---------------- BN+ReLU+fp16+DWT ----------------
__global__ void dwt_k(const float* __restrict__ rtmp, const float* __restrict__ g,
                      const float* __restrict__ beta, __half* __restrict__ dwt) {
    int idx = blockIdx.x * blockDim.x + threadIdx.x;
    if (idx >= BB * C4 * P2) return;
    int c = idx & 127;
    int p = (idx >> 7) % P2;
    int b = idx / (C4 * P2);
    int y2 = p / 28;
    int x2 = p % 28;
    float s = g[c] * rsqrtf(1.f + 1e-5f);
    float bt = beta[c];
    const __half hhalf = __float2half(0.5f);
    __half xh[2][2];
    #pragma unroll
    for (int dy = 0; dy < 2; dy++)
        #pragma unroll
        for (int dx = 0; dx < 2; dx++) {
            int n = (2 * y2 + dy) * 56 + (2 * x2 + dx);
            float v = rtmp[((long)(b * NN + n)) * C4 + c];
            v = fmaxf(v * s + bt, 0.f);
            xh[dy][dx] = __hmul(__float2half(v), hhalf);
        }
    __half x1 = xh[0][0], x2h = xh[1][0], x3 = xh[0][1], x4 = xh[1][1];
    __half ll = __hadd(__hadd(__hadd(x1, x2h), x3), x4);
    __half hl = __hadd(__hadd(__hsub(__hneg(x1), x2h), x3), x4);
    __half lh = __hadd(__hsub(__hadd(__hneg(x1), x2h), x3), x4);
    __half hh = __hadd(__hsub(__hsub(x1, x2h), x3), x4);
    long base = ((long)(b * P2 + p) << 9) + c;
    dwt[base]       = ll;
    dwt[base + 128] = hl;
    dwt[base + 256] = lh;
    dwt[base + 384] = hh;
}

// ---------------- IDWT -> cath[:, 512:] ----------------
__global__ void idwt_k(const __half* __restrict__ c3, __half* __restrict__ cat) {
    int idx = blockIdx.x * blockDim.x + threadIdx.x;
    if (idx >= BB * C4 * P2) return;
    int c = idx & 127;
    int p = (idx >> 7) % P2;
    int b = idx / (C4 * P2);
    int y2 = p / 28;
    int x2 = p % 28;
    long base = ((long)(b * P2 + p) << 9) + c;
    __half ll = c3[base], hl = c3[base + 128], lh = c3[base + 256], hh = c3[base + 384];
    const __half hhalf = __float2half(0.5f);
    __half p1 = __hmul(__hadd(__hsub(__hsub(ll, hl), lh), hh), hhalf);
    __half p2 = __hmul(__hsub(__hadd(__hsub(ll, hl), lh), hh), hhalf);
    __half p3 = __hmul(__hsub(__hsub(__hadd(ll, hl), lh), hh), hhalf);
    __half p4 = __hmul(__hadd(__hadd(__hadd(ll, hl), lh), hh), hhalf);
    int n00 = (2 * y2) * 56 + 2 * x2;
    long cb = ((long)(b * NN)) * 640 + 512 + c;
    cat[cb + (long)n00 * 640]        = p1;
    cat[cb + (long)(n00 + 1) * 640]  = p3;
    cat[cb + (long)(n00 + 56) * 640] = p2;
    cat[cb + (long)(n00 + 57) * 640] = p4;
}

// ---------------- LayerNorm ----------------
__global__ void layernorm_k(const float* __restrict__ buf, const float* __restrict__ g,
                            const float* __restrict__ bta, __half* __restrict__ outh) {
    int row = blockIdx.x;
    const float* p = buf + (long)row * CC;
    __shared__ float red[16];
    int tid = threadIdx.x;
    float v = p[tid];
    float s = v;
    #pragma unroll
    for (int o = 16; o > 0; o >>= 1) s += __shfl_xor_sync(~0u, s, o);
    if ((tid & 31) == 0) red[tid >> 5] = s;
    __syncthreads();
    if (tid < 16) {
        float t = red[tid];
        #pragma unroll
        for (int o = 8; o > 0; o >>= 1) t += __shfl_xor_sync(0xffffu, t, o);
        if (tid == 0) red[0] = t;
    }
    __syncthreads();
    float mu = red[0] * (1.f / 512.f);
    __syncthreads();
    float d = v - mu;
    float s2 = d * d;
    #pragma unroll
    for (int o = 16; o > 0; o >>= 1) s2 += __shfl_xor_sync(~0u, s2, o);
    if ((tid & 31) == 0) red[tid >> 5] = s2;
    __syncthreads();
    if (tid < 16) {
        float t = red[tid];
        #pragma unroll
        for (int o = 8; o > 0; o >>= 1) t += __shfl_xor_sync(0xffffu, t, o);
        if (tid == 0) red[0] = t;
    }
    __syncthreads();
    float var = red[0] * (1.f / 512.f);
    outh[(long)row * CC + tid] = __float2half(d * (1.f / sqrtf(var + 1e-5f)) * g[tid] + bta[tid]);
}

// =====================================================================
// WMMA attention (unchanged)
// =====================================================================
#define ATTN_SMEM (64*80*2 + 224*80*2*2 + 64*240*2 + 64*232*4)
__global__ __launch_bounds__(256)
void attn_w(const __half* __restrict__ qh, const __half* __restrict__ kvh,
            __half* __restrict__ cat) {
    extern __shared__ char smem[];
    __half* qs  = (__half*)smem;
    __half* ks  = (__half*)(smem + 10240);
    __half* vs  = (__half*)(smem + 10240 + 35840);
    __half* Ps  = (__half*)(smem + 10240 + 71680);
    float*  Ss  = (float*)(smem + 10240 + 71680 + 30720);
    int b = blockIdx.x >> 3;
    int h = blockIdx.x & 7;
    int n0 = blockIdx.y * 64;
    int tid = threadIdx.x;
    int warp = tid >> 5;
    int lane = tid & 31;

    #pragma unroll
    for (int i = 0; i < 2; i++) {
        int c = tid + i * 256;
        int row = c >> 3;
        int off = (c & 7) * 8;
        cp16(s2u(&qs[row * 80 + off]), &qh[((long)(b * NN + n0 + row) << 9) + h * 64 + off]);
    }
    #pragma unroll
    for (int i = 0; i < 7; i++) {
        int c = tid + i * 256;
        int row = c >> 3;
        int off = (c & 7) * 8;
        bool ok = row < MKV;
        int rc = ok ? row : 0;
        const __half* base = &kvh[((long)(b * MKV + rc) << 10) + h * 64 + off];
        cp16p(s2u(&ks[row * 80 + off]), base, ok);
        cp16p(s2u(&vs[row * 80 + off]), base + 512, ok);
    }
    cpcommit(); cpwait0();
    __syncthreads();

    {
        int mr = warp >> 1;
        int nh = warp & 1;
        wmma::fragment<wmma::accumulator, 16, 16, 16, float> sacc[7];
        #pragma unroll
        for (int j = 0; j < 7; j++) wmma::fill_fragment(sacc[j], 0.f);
        #pragma unroll
        for (int kk = 0; kk < 64; kk += 16) {
            wmma::fragment<wmma::matrix_a, 16, 16, 16, __half, wmma::row_major> af;
            wmma::load_matrix_sync(af, &qs[(mr * 16) * 80 + kk], 80);
            #pragma unroll
            for (int j = 0; j < 7; j++) {
                wmma::fragment<wmma::matrix_b, 16, 16, 16, __half, wmma::col_major> bf;
                wmma::load_matrix_sync(bf, &ks[((nh * 7 + j) * 16) * 80 + kk], 80);
                wmma::mma_sync(sacc[j], af, bf, sacc[j]);
            }
        }
        #pragma unroll
        for (int j = 0; j < 7; j++)
            wmma::store_matrix_sync(&Ss[(mr * 16) * 232 + (nh * 7 + j) * 16], sacc[j], 232,
                                    wmma::mem_row_major);
    }
    __syncthreads();

    for (int it = 0; it < 8; it++) {
        int r = it * 8 + warp;
        float sv[7];
        float mx = -1e30f;
        #pragma unroll
        for (int j = 0; j < 7; j++) {
            int col = lane + 32 * j;
            sv[j] = Ss[r * 232 + col] * 0.125f;
            if (col < MKV) mx = fmaxf(mx, sv[j]);
        }
        #pragma unroll
        for (int o = 16; o > 0; o >>= 1) mx = fmaxf(mx, __shfl_xor_sync(~0u, mx, o));
        float sum = 0.f;
        float pr[7];
        #pragma unroll
        for (int j = 0; j < 7; j++) {
            int col = lane + 32 * j;
            pr[j] = (col < MKV) ? __expf(sv[j] - mx) : 0.f;
            sum += pr[j];
        }
        #pragma unroll
        for (int o = 16; o > 0; o >>= 1) sum += __shfl_xor_sync(~0u, sum, o);
        float inv = 1.f / sum;
        #pragma unroll
        for (int j = 0; j < 7; j++) {
            int col = lane + 32 * j;
            Ps[r * 240 + col] = __float2half(pr[j] * inv);
        }
    }
    __syncthreads();

    {
        int mr = warp >> 1;
        int nc = warp & 1;
        wmma::fragment<wmma::accumulator, 16, 16, 16, float> oacc[2];
        #pragma unroll
        for (int j = 0; j < 2; j++) wmma::fill_fragment(oacc[j], 0.f);
        #pragma unroll
        for (int k = 0; k < 14; k++) {
            wmma::fragment<wmma::matrix_a, 16, 16, 16, __half, wmma::row_major> af;
            wmma::load_matrix_sync(af, &Ps[(mr * 16) * 240 + k * 16], 240);
            #pragma unroll
            for (int j = 0; j < 2; j++) {
                wmma::fragment<wmma::matrix_b, 16, 16, 16, __half, wmma::row_major> bf;
                wmma::load_matrix_sync(bf, &vs[(k * 16) * 80 + (nc * 2 + j) * 16], 80);
                wmma::mma_sync(oacc[j], af, bf, oacc[j]);
            }
        }
        float* Es = Ss + warp * 384;
        #pragma unroll
        for (int j = 0; j < 2; j++) {
            wmma::store_matrix_sync(Es, oacc[j], 24, wmma::mem_row_major);
            __syncwarp();
            #pragma unroll
            for (int e = 0; e < 8; e++) {
                int idx = lane + e * 32;
                int r = idx >> 4;
                int c = idx & 15;
                int m = n0 + mr * 16 + r;
                int n = (nc * 2 + j) * 16 + c;
                cat[((long)(b * NN + m)) * 640 + h * 64 + n] = __float2half(Es[r * 24 + c]);
            }
            __syncwarp();
        }
    }
}

// ---------------- launch ----------------
extern "C" void kernel_launch(void* const* d_in, const int* in_sizes, int n_in,
                              void* d_out, int out_size) {
    const float* x           = (const float*)d_in[0];
    const float* reduce_w    = (const float*)d_in[3];
    const float* reduce_b    = (const float*)d_in[4];
    const float* reduce_g    = (const float*)d_in[5];
    const float* reduce_beta = (const float*)d_in[6];
    const float* filter_w    = (const float*)d_in[7];
    const float* filter_b    = (const float*)d_in[8];
    const float* filter_g    = (const float*)d_in[9];
    const float* filter_beta = (const float*)d_in[10];
    const float* q_w         = (const float*)d_in[11];
    const float* q_b         = (const float*)d_in[12];
    const float* ln_g        = (const float*)d_in[13];
    const float* ln_b        = (const float*)d_in[14];
    const float* kv_w        = (const float*)d_in[15];
    const float* kv_b        = (const float*)d_in[16];
    const float* kve_w       = (const float*)d_in[17];
    const float* kve_b       = (const float*)d_in[18];
    const float* proj_w      = (const float*)d_in[19];
    const float* proj_b      = (const float*)d_in[20];
    float* out = (float*)d_out;

    __half *xh, *qh, *dwtbuf, *c3, *kvinh, *kvh, *cath;
    __half *qwh, *rwh, *fwh, *kvewh, *kvwh, *pwh;
    float *rtmp, *kvin;
    cudaGetSymbolAddress((void**)&xh,    g_xh);
    cudaGetSymbolAddress((void**)&qh,    g_qh);
    cudaGetSymbolAddress((void**)&rtmp,  g_rtmp);
    cudaGetSymbolAddress((void**)&dwtbuf,g_dwt);
    cudaGetSymbolAddress((void**)&c3,    g_c3);
    cudaGetSymbolAddress((void**)&kvin,  g_kvin);
    cudaGetSymbolAddress((void**)&kvinh, g_kvinh);
    cudaGetSymbolAddress((void**)&kvh,   g_kvh);
    cudaGetSymbolAddress((void**)&cath,  g_cath);
    cudaGetSymbolAddress((void**)&qwh,   g_qwh);
    cudaGetSymbolAddress((void**)&rwh,   g_rwh);
    cudaGetSymbolAddress((void**)&fwh,   g_fwh);
    cudaGetSymbolAddress((void**)&kvewh, g_kvewh);
    cudaGetSymbolAddress((void**)&kvwh,  g_kvwh);
    cudaGetSymbolAddress((void**)&pwh,   g_pwh);

    static int inited = 0;
    if (!inited) {
        cudaFuncSetAttribute(gemm16<float>, cudaFuncAttributeMaxDynamicSharedMemorySize, GEMM_SMEM);
        cudaFuncSetAttribute(gemm16<__half>, cudaFuncAttributeMaxDynamicSharedMemorySize, GEMM_SMEM);
        cudaFuncSetAttribute(conv3_g, cudaFuncAttributeMaxDynamicSharedMemorySize, GEMM_SMEM);
        cudaFuncSetAttribute(kve_g, cudaFuncAttributeMaxDynamicSharedMemorySize, GEMM_SMEM);
        cudaFuncSetAttribute(attn_w, cudaFuncAttributeMaxDynamicSharedMemorySize, ATTN_SMEM);
        inited = 1;
    }

    f2h<<<(MTOK * CC + 255) / 256, 256>>>(x, xh, MTOK * CC);
    f2h<<<(CC * CC + 255) / 256, 256>>>(q_w, qwh, CC * CC);
    f2h<<<(C4 * CC + 255) / 256, 256>>>(reduce_w, rwh, C4 * CC);
    f2h<<<(2 * CC * CC + 255) / 256, 256>>>(kv_w, kvwh, 2 * CC * CC);
    f2h<<<(CC * (CC + C4) + 255) / 256, 256>>>(proj_w, pwh, CC * (CC + C4));
    reorder_w3<<<(512 * 4608 + 255) / 256, 256>>>(filter_w, fwh);
    reorder_w2<<<(512 * 2048 + 255) / 256, 256>>>(kve_w, kvewh);

    // 1. q
    gemm16<__half><<<dim3(4, 98), 256, GEMM_SMEM>>>(xh, qwh, q_b, qh, MTOK, CC, CC, CC);
    // 2. reduce
    gemm16<float><<<dim3(1, 98), 256, GEMM_SMEM>>>(xh, rwh, reduce_b, rtmp, MTOK, C4, CC, C4);
    // 3. DWT
    dwt_k<<<(BB * C4 * P2 + 255) / 256, 256>>>(rtmp, reduce_g, reduce_beta, dwtbuf);
    // 4. conv3
    conv3_g<<<dim3(4, 25), 256, GEMM_SMEM>>>(dwtbuf, fwh, filter_b, filter_g, filter_beta, c3);
    // 5. IDWT
    idwt_k<<<(BB * C4 * P2 + 255) / 256, 256>>>(c3, cath);
    // 6. kve
    kve_g<<<dim3(4, 7), 256, GEMM_SMEM>>>(c3, kvewh, kve_b, kvin);
    // 7. LN
    layernorm_k<<<BB * MKV, 512>>>(kvin, ln_g, ln_b, kvinh);
    // 8. kv
    gemm16<__half><<<dim3(8, 7), 256, GEMM_SMEM>>>(kvinh, kvwh, kv_b, kvh, BB * MKV, 2 * CC, CC, 2 * CC);
    // 9. attention
    attn_w<<<dim3(BB * NHEADS, 49), 256, ATTN_SMEM>>>(qh, kvh, cath);
    // 10. proj
    gemm16<float><<<dim3(4, 98), 256, GEMM_SMEM>>>(cath, pwh, proj_b, out, MTOK, CC, CC + C4, CC);
}

// round 7
// speedup vs baseline: 1.1091x; 1.1091x over previous
#include <cuda_runtime.h>
#include <cuda_fp16.h>
#include <mma.h>
#include <cstdint>
using namespace nvcuda;

#define BB 8
#define NN 3136
#define CC 512
#define C4 128
#define NHEADS 8
#define P2 784
#define MKV 196
#define MTOK (BB*NN)

// ---------------- scratch ----------------
__device__ __half g_xh  [MTOK*CC];
__device__ __half g_qh  [MTOK*CC];
__device__ float  g_rtmp[MTOK*C4];
__device__ __half g_dwt [BB*P2*CC];       // NHWC
__device__ __half g_c3  [BB*P2*CC];       // NHWC
__device__ float  g_kvin[BB*MKV*CC];
__device__ __half g_kvinh[BB*MKV*CC];
__device__ __half g_kvh [BB*MKV*2*CC];
__device__ __half g_cath[MTOK*(CC+C4)];
__device__ __half g_qwh  [CC*CC];
__device__ __half g_rwh  [C4*CC];
__device__ __half g_fwh  [CC*CC*9];       // [oc][kyx][ic]
__device__ __half g_kvewh[CC*CC*4];       // [oc][kyx][ic]
__device__ __half g_kvwh [2*CC*CC];
__device__ __half g_pwh  [CC*(CC+C4)];

// ---------------- cp.async helpers ----------------
__device__ __forceinline__ unsigned int s2u(const void* p) {
    return (unsigned int)__cvta_generic_to_shared(p);
}
__device__ __forceinline__ void cp16(unsigned int d, const void* s) {
    asm volatile("cp.async.cg.shared.global [%0], [%1], 16;" :: "r"(d), "l"(s) : "memory");
}
__device__ __forceinline__ void cp16p(unsigned int d, const void* s, bool pred) {
    int sz = pred ? 16 : 0;
    asm volatile("cp.async.cg.shared.global [%0], [%1], 16, %2;" :: "r"(d), "l"(s), "r"(sz) : "memory");
}
__device__ __forceinline__ void cpcommit() { asm volatile("cp.async.commit_group;" ::: "memory"); }
__device__ __forceinline__ void cpwait0() { asm volatile("cp.async.wait_group 0;" ::: "memory"); }
__device__ __forceinline__ void cpwait1() { asm volatile("cp.async.wait_group 1;" ::: "memory"); }

// ---------------- conversion kernels ----------------
__global__ void f2h(const float* __restrict__ s, __half* __restrict__ d, int n) {
    int i = blockIdx.x * blockDim.x + threadIdx.x;
    if (i < n) d[i] = __float2half(s[i]);
}
__global__ void reorder_w3(const float* __restrict__ w, __half* __restrict__ o) {
    int idx = blockIdx.x * 256 + threadIdx.x;
    if (idx >= 512 * 4608) return;
    int oc = idx / 4608;
    int r = idx - oc * 4608;
    int kyx = r >> 9;
    int ic = r & 511;
    o[idx] = __float2half(w[((long)(oc * 512 + ic)) * 9 + kyx]);
}
__global__ void reorder_w2(const float* __restrict__ w, __half* __restrict__ o) {
    int idx = blockIdx.x * 256 + threadIdx.x;
    if (idx >= 512 * 2048) return;
    int oc = idx >> 11;
    int r = idx & 2047;
    int kyx = r >> 9;
    int ic = r & 511;
    o[idx] = __float2half(w[((long)(oc * 512 + ic)) * 4 + kyx]);
}

__device__ __forceinline__ void st_out(float* p, float v) { *p = v; }
__device__ __forceinline__ void st_out(__half* p, float v) { *p = __float2half(v); }

// =====================================================================
// gemm core: 128x128 block tile, BK=32, 3-stage cp.async, 8 warps 64x32
// As/Bs: 3 x 128 x 48 halves each; Es: 8 x 384 floats after them
// =====================================================================
#define GEMM_SMEM (3*128*48*2*2 + 8*384*4)
typedef wmma::fragment<wmma::accumulator, 16, 16, 16, float> AccFrag;

template<typename LT>
__device__ __forceinline__ void gemm_core(char* smem, int KT, LT loadTile,
                                          AccFrag (&acc)[4][2], int wr, int wc) {
    __half* As = (__half*)smem;
    __half* Bs = (__half*)(smem + 36864);
    #pragma unroll
    for (int i = 0; i < 4; i++)
        #pragma unroll
        for (int j = 0; j < 2; j++) wmma::fill_fragment(acc[i][j], 0.f);
    loadTile(0, 0); cpcommit();
    if (KT > 1) { loadTile(1, 1); cpcommit(); }
    for (int kt = 0; kt < KT; kt++) {
        if (kt < KT - 1) cpwait1(); else cpwait0();
        __syncthreads();
        if (kt + 2 < KT) { loadTile(kt + 2, (kt + 2) % 3); cpcommit(); }
        int cur = kt % 3;
        #pragma unroll
        for (int kk = 0; kk < 32; kk += 16) {
            wmma::fragment<wmma::matrix_a, 16, 16, 16, __half, wmma::row_major> af[4];
            wmma::fragment<wmma::matrix_b, 16, 16, 16, __half, wmma::col_major> bf[2];
            #pragma unroll
            for (int i = 0; i < 4; i++)
                wmma::load_matrix_sync(af[i], &As[(cur * 128 + wr * 64 + i * 16) * 48 + kk], 48);
            #pragma unroll
            for (int j = 0; j < 2; j++)
                wmma::load_matrix_sync(bf[j], &Bs[(cur * 128 + wc * 32 + j * 16) * 48 + kk], 48);
            #pragma unroll
            for (int i = 0; i < 4; i++)
                #pragma unroll
                for (int j = 0; j < 2; j++)
                    wmma::mma_sync(acc[i][j], af[i], bf[j], acc[i][j]);
        }
        __syncthreads();
    }
}

// =====================================================================
// gemm16: C[m,n] = sum_k A[m,k] B[n,k] + bias[n]
// =====================================================================
template<typename OT>
__global__ __launch_bounds__(256)
void gemm16(const __half* __restrict__ A, const __half* __restrict__ B,
            const float* __restrict__ bias, OT* __restrict__ C,
            int M, int N, int K, int ldc) {
    extern __shared__ char smem[];
    __half* As = (__half*)smem;
    __half* Bs = (__half*)(smem + 36864);
    float*  Es = (float*)(smem + 73728);
    int tid = threadIdx.x;
    int warp = tid >> 5;
    int lane = tid & 31;
    int wr = warp & 1;
    int wc = warp >> 1;
    int m0 = blockIdx.y * 128;
    int n0 = blockIdx.x * 128;
    AccFrag acc[4][2];
    auto loadTile = [&](int kt, int buf) {
        int k0 = kt << 5;
        #pragma unroll
        for (int i = 0; i < 2; i++) {
            int c = tid + i * 256;
            int row = c >> 2;
            int off = (c & 3) * 8;
            int m = m0 + row;
            bool ok = (m < M);
            cp16p(s2u(&As[(buf * 128 + row) * 48 + off]), &A[(long)(ok ? m : 0) * K + k0 + off], ok);
            cp16(s2u(&Bs[(buf * 128 + row) * 48 + off]), &B[(long)(n0 + row) * K + k0 + off]);
        }
    };
    gemm_core(smem, K >> 5, loadTile, acc, wr, wc);
    #pragma unroll
    for (int i = 0; i < 4; i++)
        #pragma unroll
        for (int j = 0; j < 2; j++) {
            wmma::store_matrix_sync(&Es[warp * 384], acc[i][j], 24, wmma::mem_row_major);
            __syncwarp();
            #pragma unroll
            for (int e = 0; e < 8; e++) {
                int idx = lane + e * 32;
                int r = idx >> 4;
                int c = idx & 15;
                int m = m0 + wr * 64 + i * 16 + r;
                int n = n0 + wc * 32 + j * 16 + c;
                if (m < M) st_out(&C[(long)m * ldc + n], Es[warp * 384 + r * 24 + c] + bias[n]);
            }
            __syncwarp();
        }
}

// =====================================================================
// conv3x3 implicit GEMM (NHWC) + BN + ReLU -> fp16; M=6272,N=512,K=4608
// =====================================================================
__global__ __launch_bounds__(256)
void conv3_g(const __half* __restrict__ dwt, const __half* __restrict__ w,
             const float* __restrict__ cb, const float* __restrict__ cg,
             const float* __restrict__ cbeta, __half* __restrict__ out) {
    extern __shared__ char smem[];
    __half* As = (__half*)smem;
    __half* Bs = (__half*)(smem + 36864);
    float*  Es = (float*)(smem + 73728);
    int tid = threadIdx.x;
    int warp = tid >> 5;
    int lane = tid & 31;
    int wr = warp & 1;
    int wc = warp >> 1;
    int m0 = blockIdx.y * 128;
    int n0 = blockIdx.x * 128;
    int pre_b[2], pre_y[2], pre_x[2];
    #pragma unroll
    for (int i = 0; i < 2; i++) {
        int c = tid + i * 256;
        int row = c >> 2;
        int m = m0 + row;
        int b = m / P2;
        int p = m - b * P2;
        pre_b[i] = b;
        pre_y[i] = p / 28;
        pre_x[i] = p - (p / 28) * 28;
    }
    AccFrag acc[4][2];
    auto loadTile = [&](int kt, int buf) {
        int k0 = kt << 5;
        #pragma unroll
        for (int i = 0; i < 2; i++) {
            int c = tid + i * 256;
            int row = c >> 2;
            int off = (c & 3) * 8;
            int k = k0 + off;
            int kyx = k >> 9;
            int ic = k & 511;
            int ky = kyx / 3;
            int kx = kyx - ky * 3;
            int iy = pre_y[i] + ky - 1;
            int ix = pre_x[i] + kx - 1;
            bool ok = (iy >= 0 && iy < 28 && ix >= 0 && ix < 28);
            int iyc = ok ? iy : 0;
            int ixc = ok ? ix : 0;
            cp16p(s2u(&As[(buf * 128 + row) * 48 + off]),
                  &dwt[((long)(pre_b[i] * P2 + iyc * 28 + ixc) << 9) + ic], ok);
            cp16(s2u(&Bs[(buf * 128 + row) * 48 + off]), &w[(long)(n0 + row) * 4608 + k0 + off]);
        }
    };
    gemm_core(smem, 144, loadTile, acc, wr, wc);
    const float invs = rsqrtf(1.f + 1e-5f);
    #pragma unroll
    for (int i = 0; i < 4; i++)
        #pragma unroll
        for (int j = 0; j < 2; j++) {
            wmma::store_matrix_sync(&Es[warp * 384], acc[i][j], 24, wmma::mem_row_major);
            __syncwarp();
            #pragma unroll
            for (int e = 0; e < 8; e++) {
                int idx = lane + e * 32;
                int r = idx >> 4;
                int c = idx & 15;
                int m = m0 + wr * 64 + i * 16 + r;
                int n = n0 + wc * 32 + j * 16 + c;
                float v = Es[warp * 384 + r * 24 + c] + cb[n];
                v = v * (cg[n] * invs) + cbeta[n];
                out[((long)m << 9) + n] = __float2half(fmaxf(v, 0.f));
            }
            __syncwarp();
        }
}

// =====================================================================
// kve 2x2 s2 conv implicit GEMM; M=1568,N=512,K=2048 -> fp32 + bias
// =====================================================================
__global__ __launch_bounds__(256)
void kve_g(const __half* __restrict__ c3, const __half* __restrict__ w,
           const float* __restrict__ bias, float* __restrict__ out) {
    extern __shared__ char smem[];
    __half* As = (__half*)smem;
    __half* Bs = (__half*)(smem + 36864);
    float*  Es = (float*)(smem + 73728);
    int tid = threadIdx.x;
    int warp = tid >> 5;
    int lane = tid & 31;
    int wr = warp & 1;
    int wc = warp >> 1;
    int m0 = blockIdx.y * 128;
    int n0 = blockIdx.x * 128;
    int pre_s[2];
    bool pre_v[2];
    #pragma unroll
    for (int i = 0; i < 2; i++) {
        int c = tid + i * 256;
        int row = c >> 2;
        int m = m0 + row;
        pre_v[i] = (m < BB * MKV);
        int mm = pre_v[i] ? m : 0;
        int b = mm / MKV;
        int p = mm - b * MKV;
        int oy = p / 14;
        int ox = p - (p / 14) * 14;
        pre_s[i] = b * P2 + 2 * oy * 28 + 2 * ox;
    }
    AccFrag acc[4][2];
    auto loadTile = [&](int kt, int buf) {
        int k0 = kt << 5;
        #pragma unroll
        for (int i = 0; i < 2; i++) {
            int c = tid + i * 256;
            int row = c >> 2;
            int off = (c & 3) * 8;
            int k = k0 + off;
            int kyx = k >> 9;
            int ic = k & 511;
            int ky = kyx >> 1;
            int kx = kyx & 1;
            cp16p(s2u(&As[(buf * 128 + row) * 48 + off]),
                  &c3[((long)(pre_s[i] + ky * 28 + kx) << 9) + ic], pre_v[i]);
            cp16(s2u(&Bs[(buf * 128 + row) * 48 + off]), &w[(long)(n0 + row) * 2048 + k0 + off]);
        }
    };
    gemm_core(smem, 64, loadTile, acc, wr, wc);
    #pragma unroll
    for (int i = 0; i < 4; i++)
        #pragma unroll
        for (int j = 0; j < 2; j++) {
            wmma::store_matrix_sync(&Es[warp * 384], acc[i][j], 24, wmma::mem_row_major);
            __syncwarp();
            #pragma unroll
            for (int e = 0; e < 8; e++) {
                int idx = lane + e * 32;
                int r = idx >> 4;
                int c = idx & 15;
                int m = m0 + wr * 64 + i * 16 + r;
                int n = n0 + wc * 32 + j * 16 + c;
                if (m < BB * MKV) out[(long)m * CC + n] = Es[warp * 384 + r * 24 + c] + bias[n];
            }
            __syncwarp();
        }
}

// ---------------- BN+ReLU+fp16+DWT ----------------
__global__ void dwt_k(const float* __restrict__ rtmp, const float* __restrict__ g,
                      const float* __restrict__ beta, __half* __restrict__ dwt) {
    int idx = blockIdx.x * blockDim.x + threadIdx.x;
    if (idx >= BB * C4 * P2) return;
    int c = idx & 127;
    int p = (idx >> 7) % P2;
    int b = idx / (C4 * P2);
    int y2 = p / 28;
    int x2 = p % 28;
    float s = g[c] * rsqrtf(1.f + 1e-5f);
    float bt = beta[c];
    const __half hhalf = __float2half(0.5f);
    __half xh[2][2];
    #pragma unroll
    for (int dy = 0; dy < 2; dy++)
        #pragma unroll
        for (int dx = 0; dx < 2; dx++) {
            int n = (2 * y2 + dy) * 56 + (2 * x2 + dx);
            float v = rtmp[((long)(b * NN + n)) * C4 + c];
            v = fmaxf(v * s + bt, 0.f);
            xh[dy][dx] = __hmul(__float2half(v), hhalf);
        }
    __half x1 = xh[0][0], x2h = xh[1][0], x3 = xh[0][1], x4 = xh[1][1];
    __half ll = __hadd(__hadd(__hadd(x1, x2h), x3), x4);
    __half hl = __hadd(__hadd(__hsub(__hneg(x1), x2h), x3), x4);
    __half lh = __hadd(__hsub(__hadd(__hneg(x1), x2h), x3), x4);
    __half hh = __hadd(__hsub(__hsub(x1, x2h), x3), x4);
    long base = ((long)(b * P2 + p) << 9) + c;
    dwt[base]       = ll;
    dwt[base + 128] = hl;
    dwt[base + 256] = lh;
    dwt[base + 384] = hh;
}

// ---------------- IDWT -> cath[:, 512:] ----------------
__global__ void idwt_k(const __half* __restrict__ c3, __half* __restrict__ cat) {
    int idx = blockIdx.x * blockDim.x + threadIdx.x;
    if (idx >= BB * C4 * P2) return;
    int c = idx & 127;
    int p = (idx >> 7) % P2;
    int b = idx / (C4 * P2);
    int y2 = p / 28;
    int x2 = p % 28;
    long base = ((long)(b * P2 + p) << 9) + c;
    __half ll = c3[base], hl = c3[base + 128], lh = c3[base + 256], hh = c3[base + 384];
    const __half hhalf = __float2half(0.5f);
    __half p1 = __hmul(__hadd(__hsub(__hsub(ll, hl), lh), hh), hhalf);
    __half p2 = __hmul(__hsub(__hadd(__hsub(ll, hl), lh), hh), hhalf);
    __half p3 = __hmul(__hsub(__hsub(__hadd(ll, hl), lh), hh), hhalf);
    __half p4 = __hmul(__hadd(__hadd(__hadd(ll, hl), lh), hh), hhalf);
    int n00 = (2 * y2) * 56 + 2 * x2;
    long cb = ((long)(b * NN)) * 640 + 512 + c;
    cat[cb + (long)n00 * 640]        = p1;
    cat[cb + (long)(n00 + 1) * 640]  = p3;
    cat[cb + (long)(n00 + 56) * 640] = p2;
    cat[cb + (long)(n00 + 57) * 640] = p4;
}

// ---------------- LayerNorm ----------------
__global__ void layernorm_k(const float* __restrict__ buf, const float* __restrict__ g,
                            const float* __restrict__ bta, __half* __restrict__ outh) {
    int row = blockIdx.x;
    const float* p = buf + (long)row * CC;
    __shared__ float red[16];
    int tid = threadIdx.x;
    float v = p[tid];
    float s = v;
    #pragma unroll
    for (int o = 16; o > 0; o >>= 1) s += __shfl_xor_sync(~0u, s, o);
    if ((tid & 31) == 0) red[tid >> 5] = s;
    __syncthreads();
    if (tid < 16) {
        float t = red[tid];
        #pragma unroll
        for (int o = 8; o > 0; o >>= 1) t += __shfl_xor_sync(0xffffu, t, o);
        if (tid == 0) red[0] = t;
    }
    __syncthreads();
    float mu = red[0] * (1.f / 512.f);
    __syncthreads();
    float d = v - mu;
    float s2 = d * d;
    #pragma unroll
    for (int o = 16; o > 0; o >>= 1) s2 += __shfl_xor_sync(~0u, s2, o);
    if ((tid & 31) == 0) red[tid >> 5] = s2;
    __syncthreads();
    if (tid < 16) {
        float t = red[tid];
        #pragma unroll
        for (int o = 8; o > 0; o >>= 1) t += __shfl_xor_sync(0xffffu, t, o);
        if (tid == 0) red[0] = t;
    }
    __syncthreads();
    float var = red[0] * (1.f / 512.f);
    outh[(long)row * CC + tid] = __float2half(d * (1.f / sqrtf(var + 1e-5f)) * g[tid] + bta[tid]);
}

// =====================================================================
// WMMA attention (unchanged)
// =====================================================================
#define ATTN_SMEM (64*80*2 + 224*80*2*2 + 64*240*2 + 64*232*4)
__global__ __launch_bounds__(256)
void attn_w(const __half* __restrict__ qh, const __half* __restrict__ kvh,
            __half* __restrict__ cat) {
    extern __shared__ char smem[];
    __half* qs  = (__half*)smem;
    __half* ks  = (__half*)(smem + 10240);
    __half* vs  = (__half*)(smem + 10240 + 35840);
    __half* Ps  = (__half*)(smem + 10240 + 71680);
    float*  Ss  = (float*)(smem + 10240 + 71680 + 30720);
    int b = blockIdx.x >> 3;
    int h = blockIdx.x & 7;
    int n0 = blockIdx.y * 64;
    int tid = threadIdx.x;
    int warp = tid >> 5;
    int lane = tid & 31;

    #pragma unroll
    for (int i = 0; i < 2; i++) {
        int c = tid + i * 256;
        int row = c >> 3;
        int off = (c & 7) * 8;
        cp16(s2u(&qs[row * 80 + off]), &qh[((long)(b * NN + n0 + row) << 9) + h * 64 + off]);
    }
    #pragma unroll
    for (int i = 0; i < 7; i++) {
        int c = tid + i * 256;
        int row = c >> 3;
        int off = (c & 7) * 8;
        bool ok = row < MKV;
        int rc = ok ? row : 0;
        const __half* base = &kvh[((long)(b * MKV + rc) << 10) + h * 64 + off];
        cp16p(s2u(&ks[row * 80 + off]), base, ok);
        cp16p(s2u(&vs[row * 80 + off]), base + 512, ok);
    }
    cpcommit(); cpwait0();
    __syncthreads();

    {
        int mr = warp >> 1;
        int nh = warp & 1;
        wmma::fragment<wmma::accumulator, 16, 16, 16, float> sacc[7];
        #pragma unroll
        for (int j = 0; j < 7; j++) wmma::fill_fragment(sacc[j], 0.f);
        #pragma unroll
        for (int kk = 0; kk < 64; kk += 16) {
            wmma::fragment<wmma::matrix_a, 16, 16, 16, __half, wmma::row_major> af;
            wmma::load_matrix_sync(af, &qs[(mr * 16) * 80 + kk], 80);
            #pragma unroll
            for (int j = 0; j < 7; j++) {
                wmma::fragment<wmma::matrix_b, 16, 16, 16, __half, wmma::col_major> bf;
                wmma::load_matrix_sync(bf, &ks[((nh * 7 + j) * 16) * 80 + kk], 80);
                wmma::mma_sync(sacc[j], af, bf, sacc[j]);
            }
        }
        #pragma unroll
        for (int j = 0; j < 7; j++)
            wmma::store_matrix_sync(&Ss[(mr * 16) * 232 + (nh * 7 + j) * 16], sacc[j], 232,
                                    wmma::mem_row_major);
    }
    __syncthreads();

    for (int it = 0; it < 8; it++) {
        int r = it * 8 + warp;
        float sv[7];
        float mx = -1e30f;
        #pragma unroll
        for (int j = 0; j < 7; j++) {
            int col = lane + 32 * j;
            sv[j] = Ss[r * 232 + col] * 0.125f;
            if (col < MKV) mx = fmaxf(mx, sv[j]);
        }
        #pragma unroll
        for (int o = 16; o > 0; o >>= 1) mx = fmaxf(mx, __shfl_xor_sync(~0u, mx, o));
        float sum = 0.f;
        float pr[7];
        #pragma unroll
        for (int j = 0; j < 7; j++) {
            int col = lane + 32 * j;
            pr[j] = (col < MKV) ? __expf(sv[j] - mx) : 0.f;
            sum += pr[j];
        }
        #pragma unroll
        for (int o = 16; o > 0; o >>= 1) sum += __shfl_xor_sync(~0u, sum, o);
        float inv = 1.f / sum;
        #pragma unroll
        for (int j = 0; j < 7; j++) {
            int col = lane + 32 * j;
            Ps[r * 240 + col] = __float2half(pr[j] * inv);
        }
    }
    __syncthreads();

    {
        int mr = warp >> 1;
        int nc = warp & 1;
        wmma::fragment<wmma::accumulator, 16, 16, 16, float> oacc[2];
        #pragma unroll
        for (int j = 0; j < 2; j++) wmma::fill_fragment(oacc[j], 0.f);
        #pragma unroll
        for (int k = 0; k < 14; k++) {
            wmma::fragment<wmma::matrix_a, 16, 16, 16, __half, wmma::row_major> af;
            wmma::load_matrix_sync(af, &Ps[(mr * 16) * 240 + k * 16], 240);
            #pragma unroll
            for (int j = 0; j < 2; j++) {
                wmma::fragment<wmma::matrix_b, 16, 16, 16, __half, wmma::row_major> bf;
                wmma::load_matrix_sync(bf, &vs[(k * 16) * 80 + (nc * 2 + j) * 16], 80);
                wmma::mma_sync(oacc[j], af, bf, oacc[j]);
            }
        }
        float* Es = Ss + warp * 384;
        #pragma unroll
        for (int j = 0; j < 2; j++) {
            wmma::store_matrix_sync(Es, oacc[j], 24, wmma::mem_row_major);
            __syncwarp();
            #pragma unroll
            for (int e = 0; e < 8; e++) {
                int idx = lane + e * 32;
                int r = idx >> 4;
                int c = idx & 15;
                int m = n0 + mr * 16 + r;
                int n = (nc * 2 + j) * 16 + c;
                cat[((long)(b * NN + m)) * 640 + h * 64 + n] = __float2half(Es[r * 24 + c]);
            }
            __syncwarp();
        }
    }
}

// ---------------- launch ----------------
extern "C" void kernel_launch(void* const* d_in, const int* in_sizes, int n_in,
                              void* d_out, int out_size) {
    const float* x           = (const float*)d_in[0];
    const float* reduce_w    = (const float*)d_in[3];
    const float* reduce_b    = (const float*)d_in[4];
    const float* reduce_g    = (const float*)d_in[5];
    const float* reduce_beta = (const float*)d_in[6];
    const float* filter_w    = (const float*)d_in[7];
    const float* filter_b    = (const float*)d_in[8];
    const float* filter_g    = (const float*)d_in[9];
    const float* filter_beta = (const float*)d_in[10];
    const float* q_w         = (const float*)d_in[11];
    const float* q_b         = (const float*)d_in[12];
    const float* ln_g        = (const float*)d_in[13];
    const float* ln_b        = (const float*)d_in[14];
    const float* kv_w        = (const float*)d_in[15];
    const float* kv_b        = (const float*)d_in[16];
    const float* kve_w       = (const float*)d_in[17];
    const float* kve_b       = (const float*)d_in[18];
    const float* proj_w      = (const float*)d_in[19];
    const float* proj_b      = (const float*)d_in[20];
    float* out = (float*)d_out;

    __half *xh, *qh, *dwtbuf, *c3, *kvinh, *kvh, *cath;
    __half *qwh, *rwh, *fwh, *kvewh, *kvwh, *pwh;
    float *rtmp, *kvin;
    cudaGetSymbolAddress((void**)&xh,    g_xh);
    cudaGetSymbolAddress((void**)&qh,    g_qh);
    cudaGetSymbolAddress((void**)&rtmp,  g_rtmp);
    cudaGetSymbolAddress((void**)&dwtbuf,g_dwt);
    cudaGetSymbolAddress((void**)&c3,    g_c3);
    cudaGetSymbolAddress((void**)&kvin,  g_kvin);
    cudaGetSymbolAddress((void**)&kvinh, g_kvinh);
    cudaGetSymbolAddress((void**)&kvh,   g_kvh);
    cudaGetSymbolAddress((void**)&cath,  g_cath);
    cudaGetSymbolAddress((void**)&qwh,   g_qwh);
    cudaGetSymbolAddress((void**)&rwh,   g_rwh);
    cudaGetSymbolAddress((void**)&fwh,   g_fwh);
    cudaGetSymbolAddress((void**)&kvewh, g_kvewh);
    cudaGetSymbolAddress((void**)&kvwh,  g_kvwh);
    cudaGetSymbolAddress((void**)&pwh,   g_pwh);

    static int inited = 0;
    if (!inited) {
        cudaFuncSetAttribute(gemm16<float>, cudaFuncAttributeMaxDynamicSharedMemorySize, GEMM_SMEM);
        cudaFuncSetAttribute(gemm16<__half>, cudaFuncAttributeMaxDynamicSharedMemorySize, GEMM_SMEM);
        cudaFuncSetAttribute(conv3_g, cudaFuncAttributeMaxDynamicSharedMemorySize, GEMM_SMEM);
        cudaFuncSetAttribute(kve_g, cudaFuncAttributeMaxDynamicSharedMemorySize, GEMM_SMEM);
        cudaFuncSetAttribute(attn_w, cudaFuncAttributeMaxDynamicSharedMemorySize, ATTN_SMEM);
        inited = 1;
    }

    // launches 0-4: conversions needed up front (q gemm lands at launch #5 for ncu -s 5)
    f2h<<<(MTOK * CC + 255) / 256, 256>>>(x, xh, MTOK * CC);                 // 0
    f2h<<<(CC * CC + 255) / 256, 256>>>(q_w, qwh, CC * CC);                  // 1
    f2h<<<(C4 * CC + 255) / 256, 256>>>(reduce_w, rwh, C4 * CC);             // 2
    reorder_w3<<<(512 * 4608 + 255) / 256, 256>>>(filter_w, fwh);            // 3
    reorder_w2<<<(512 * 2048 + 255) / 256, 256>>>(kve_w, kvewh);             // 4

    // 5. q GEMM (profiled)
    gemm16<__half><<<dim3(4, 196), 256, GEMM_SMEM>>>(xh, qwh, q_b, qh, MTOK, CC, CC, CC);
    // 6. reduce GEMM
    gemm16<float><<<dim3(1, 196), 256, GEMM_SMEM>>>(xh, rwh, reduce_b, rtmp, MTOK, C4, CC, C4);
    // 7. DWT
    dwt_k<<<(BB * C4 * P2 + 255) / 256, 256>>>(rtmp, reduce_g, reduce_beta, dwtbuf);
    // 8. conv3
    conv3_g<<<dim3(4, 49), 256, GEMM_SMEM>>>(dwtbuf, fwh, filter_b, filter_g, filter_beta, c3);
    // 9. IDWT
    idwt_k<<<(BB * C4 * P2 + 255) / 256, 256>>>(c3, cath);
    // 10. kve
    kve_g<<<dim3(4, 13), 256, GEMM_SMEM>>>(c3, kvewh, kve_b, kvin);
    // 11. kv weight conversion
    f2h<<<(2 * CC * CC + 255) / 256, 256>>>(kv_w, kvwh, 2 * CC * CC);
    // 12. LN
    layernorm_k<<<BB * MKV, 512>>>(kvin, ln_g, ln_b, kvinh);
    // 13. kv GEMM
    gemm16<__half><<<dim3(8, 13), 256, GEMM_SMEM>>>(kvinh, kvwh, kv_b, kvh, BB * MKV, 2 * CC, CC, 2 * CC);
    // 14. proj weight conversion
    f2h<<<(CC * (CC + C4) + 255) / 256, 256>>>(proj_w, pwh, CC * (CC + C4));
    // 15. attention
    attn_w<<<dim3(BB * NHEADS, 49), 256, ATTN_SMEM>>>(qh, kvh, cath);
    // 16. proj
    gemm16<float><<<dim3(4, 196), 256, GEMM_SMEM>>>(cath, pwh, proj_b, out, MTOK, CC, CC + C4, CC);
}